// round 6
// baseline (speedup 1.0000x reference)
#include <cuda_runtime.h>

// Problem constants
#define TSEQ 1024
#define NB   32      // batch
#define ID   512     // input dim
#define HD   512     // hidden dim
#define GD   2048    // 4*H gate rows
#define NBLK_DIR 64  // persistent blocks per direction (8 hidden units each)
#define REC_THREADS 512

typedef unsigned long long ull;

// Scratch (device globals: no runtime allocation allowed)
__device__ float g_xw[(size_t)TSEQ * GD * NB];   // [t][g][b], 256MB
// h in k-paired layout: g_hbuf[dir][ping][kp*64 + b*2 + (u&1)], kp = u>>1
__device__ float g_hbuf[2][2][HD * NB];
__device__ unsigned g_barcnt[2];   // monotonic arrival counters (never reset)
__device__ unsigned g_bargen[2];   // monotonic generation

// ---------------------------------------------------------------------------
// packed fp32x2 FMA (Blackwell): d.xy += a.xy * b.xy
// ---------------------------------------------------------------------------
__device__ __forceinline__ void ffma2(ull& d, ull a, ull b) {
    asm("fma.rn.f32x2 %0, %1, %2, %0;" : "+l"(d) : "l"(a), "l"(b));
}
__device__ __forceinline__ float pairsum(ull v) {
    float2 f = *reinterpret_cast<float2*>(&v);
    return f.x + f.y;
}

__device__ __forceinline__ unsigned atom_add_acqrel(unsigned* p, unsigned v) {
    unsigned old;
    asm volatile("atom.acq_rel.gpu.add.u32 %0, [%1], %2;"
                 : "=r"(old) : "l"(p), "r"(v) : "memory");
    return old;
}
__device__ __forceinline__ unsigned ld_acquire(const unsigned* p) {
    unsigned v;
    asm volatile("ld.acquire.gpu.u32 %0, [%1];" : "=r"(v) : "l"(p) : "memory");
    return v;
}
__device__ __forceinline__ void st_release(unsigned* p, unsigned v) {
    asm volatile("st.release.gpu.u32 [%0], %1;" :: "l"(p), "r"(v) : "memory");
}

__device__ __forceinline__ float sigf(float x) {
    return __fdividef(1.f, 1.f + __expf(-x));
}
__device__ __forceinline__ float tanhfast(float x) {
    return __fdividef(2.f, 1.f + __expf(-2.f * x)) - 1.f;
}

// ---------------------------------------------------------------------------
// xw[t][g][b] = sum_i x[t][b][i] * W_ih[g][i] + (b_ih[g] + b_hh[g])
// Also zeroes its 2KB slice of d_out.
// ---------------------------------------------------------------------------
__global__ __launch_bounds__(256) void xw_gemm(
    const float* __restrict__ x,
    const float* __restrict__ Wih,
    const float* __restrict__ bih,
    const float* __restrict__ bhh,
    float4* __restrict__ out4)
{
    __shared__ float xs[NB * 36];
    __shared__ float ws[64 * 32];

    if (threadIdx.x < 128)
        out4[(size_t)blockIdx.x * 128 + threadIdx.x] = make_float4(0.f, 0.f, 0.f, 0.f);

    int t   = blockIdx.x >> 5;
    int g0  = (blockIdx.x & 31) << 6;
    int tid = threadIdx.x;
    int gg  = tid >> 5;
    int b   = tid & 31;

    ull acc[8];
#pragma unroll
    for (int j = 0; j < 8; j++) acc[j] = 0ull;

    const float* xt = x + (size_t)t * NB * ID;

    for (int k0 = 0; k0 < ID; k0 += 32) {
#pragma unroll
        for (int r = 0; r < 4; r++) {
            int bl = (tid >> 5) + (r << 3);
            int kk = tid & 31;
            xs[bl * 36 + kk] = xt[bl * ID + k0 + kk];
        }
#pragma unroll
        for (int r = 0; r < 8; r++) {
            int gl = (tid >> 5) + (r << 3);
            int kk = tid & 31;
            ws[gl * 32 + kk] = Wih[(size_t)(g0 + gl) * ID + k0 + kk];
        }
        __syncthreads();

#pragma unroll
        for (int kk = 0; kk < 32; kk += 4) {
            ulonglong2 xv = *(const ulonglong2*)&xs[b * 36 + kk];
#pragma unroll
            for (int j = 0; j < 8; j++) {
                ulonglong2 wv = *(const ulonglong2*)&ws[(gg * 8 + j) * 32 + kk];
                ffma2(acc[j], xv.x, wv.x);
                ffma2(acc[j], xv.y, wv.y);
            }
        }
        __syncthreads();
    }

    float* outp = g_xw + (size_t)t * GD * NB;
#pragma unroll
    for (int j = 0; j < 8; j++) {
        int g = g0 + gg * 8 + j;
        outp[g * NB + b] = pairsum(acc[j]) + bih[g] + bhh[g];
    }
}

// ---------------------------------------------------------------------------
// Global spin barrier, per direction, monotonic (graph-replay safe)
// ---------------------------------------------------------------------------
__device__ __forceinline__ void dir_barrier(int dir, unsigned gen) {
    __syncthreads();
    if (threadIdx.x == 0) {
        unsigned old = atom_add_acqrel(&g_barcnt[dir], 1u);
        if (old == gen * (unsigned)NBLK_DIR + (NBLK_DIR - 1)) {
            st_release(&g_bargen[dir], gen + 1u);
        } else {
            while ((int)(ld_acquire(&g_bargen[dir]) - (gen + 1u)) < 0) { }
        }
    }
    __syncthreads();
}

// ---------------------------------------------------------------------------
// Persistent bidirectional zoneout-LSTM recurrence, 512 threads/block.
// 128 blocks: 0..63 fwd, 64..127 bwd. Block owns 8 hidden units (32 gate rows)
// x 32 batch. 16 warps = 16 k-slices of 32 k (16 k-pairs) each.
// Lane tile: 8 rows x 4 batches (rg = lane>>3 -> rows 8rg..8rg+7,
// bg = lane&7 -> batches 4bg..4bg+3). 3 smem-bytes per FFMA2-lane.
// Each warp stages exactly the h float4 range [w*256, w*256+256) it reads.
// ---------------------------------------------------------------------------
__global__ __launch_bounds__(REC_THREADS, 1) void lstm_rec(
    const float* __restrict__ Whh, float* __restrict__ out)
{
    extern __shared__ float smem[];
    float4* wsm  = (float4*)smem;         // 4096 float4 = 64KB: [kp*16 + rowpair]
    float*  hp   = smem + 16384;          // 64KB: hp[kp*64 + b*2 + kk]
    float*  gbuf = hp + 16384;            // 64KB: [s16][row][b]
    float*  c_s  = gbuf + 16384;          // 1KB

    int bid  = blockIdx.x;
    int dir  = bid >> 6;
    int j0   = (bid & 63) << 3;
    int tid  = threadIdx.x;
    int w    = tid >> 5;        // warp = k-slice 0..15
    int lane = tid & 31;
    int rg   = lane >> 3;       // 0..3 -> rows 8rg..8rg+7
    int bg   = lane & 7;        // 0..7 -> batches 4bg..4bg+3

    // Stage W_hh: wsm[kp*16 + p] = (W[2p][2kp], W[2p][2kp+1], W[2p+1][2kp], W[2p+1][2kp+1])
    //   local row r -> global row (r>>3)*512 + j0 + (r&7)
#pragma unroll
    for (int i = 0; i < 8; i++) {
        int idx = tid + (i << 9);
        int p   = idx & 15;
        int kp  = idx >> 4;
        int rA  = 2 * p;
        int rB  = rA + 1;
        int gA  = ((rA >> 3) << 9) + j0 + (rA & 7);
        int gB  = ((rB >> 3) << 9) + j0 + (rB & 7);
        float2 a  = *(const float2*)&Whh[(size_t)gA * HD + (kp << 1)];
        float2 bb = *(const float2*)&Whh[(size_t)gB * HD + (kp << 1)];
        wsm[idx] = make_float4(a.x, a.y, bb.x, bb.y);
    }

    // cell-phase roles: warps 0..7 = unit u_l, lanes = batch
    int u_l = w;                // valid when w < 8
    int gu  = j0 + (u_l & 7);
    int hidx = (gu >> 1) * 64 + (lane << 1) + (gu & 1);

    // init c, h(step 0) = 0 in global k-paired layout (own units only)
    if (tid < 256) c_s[tid] = 0.f;
    if (w < 8) g_hbuf[dir][0][hidx] = 0.f;

    unsigned gen = ld_acquire(&g_bargen[dir]);
    dir_barrier(dir, gen);
    gen++;

    const ull* hp_u = (const ull*)hp;
    const ulonglong2* wq = (const ulonglong2*)wsm;
    const int kp0 = w << 4;                 // 16 k-pairs per warp
    const int hb_off = bg << 2;             // ull offset within a kp row

    for (int s = 0; s < TSEQ; s++) {
        int t = dir ? (TSEQ - 1 - s) : s;
        const float* xw_t = g_xw + (size_t)t * GD * NB;

        // prefetch xw for the cell phase (hidden under GEMV); warps 0..7 only
        float xg0 = 0.f, xg1 = 0.f, xg2 = 0.f, xg3 = 0.f;
        if (w < 8) {
            xg0 = xw_t[(0 * HD + gu) * NB + lane];
            xg1 = xw_t[(1 * HD + gu) * NB + lane];
            xg2 = xw_t[(2 * HD + gu) * NB + lane];
            xg3 = xw_t[(3 * HD + gu) * NB + lane];
        }

        // per-warp copy of EXACTLY its h k-slice: float4 range [w*256, w*256+256)
        {
            const float4* hsrc = (const float4*)g_hbuf[dir][s & 1];
            float4* hdst = (float4*)hp;
#pragma unroll
            for (int i = 0; i < 8; i++) {
                int idx = (w << 8) + (i << 5) + lane;
                hdst[idx] = __ldcg(&hsrc[idx]);
            }
            __syncwarp();   // order cross-lane STS -> LDS within this warp
        }

        // GEMV: 8x4 register tile per lane over 16 k-pairs
        ull acc[8][4];
#pragma unroll
        for (int i = 0; i < 8; i++)
#pragma unroll
            for (int j = 0; j < 4; j++) acc[i][j] = 0ull;

#pragma unroll 4
        for (int kp = kp0; kp < kp0 + 16; kp++) {
            ulonglong2 h0 = *(const ulonglong2*)&hp_u[(kp << 5) + hb_off];
            ulonglong2 h1 = *(const ulonglong2*)&hp_u[(kp << 5) + hb_off + 2];
#pragma unroll
            for (int j = 0; j < 4; j++) {
                ulonglong2 wv = wq[(kp << 4) + (rg << 2) + j];  // rows 8rg+2j, 8rg+2j+1
                ffma2(acc[2 * j][0],     wv.x, h0.x);
                ffma2(acc[2 * j][1],     wv.x, h0.y);
                ffma2(acc[2 * j][2],     wv.x, h1.x);
                ffma2(acc[2 * j][3],     wv.x, h1.y);
                ffma2(acc[2 * j + 1][0], wv.y, h0.x);
                ffma2(acc[2 * j + 1][1], wv.y, h0.y);
                ffma2(acc[2 * j + 1][2], wv.y, h1.x);
                ffma2(acc[2 * j + 1][3], wv.y, h1.y);
            }
        }

        // write partials, rotated columns -> all 32 banks distinct per store
        // gbuf[(w*32 + row)*32 + b], row = 8rg+i, b = 4bg + ((rg+t4)&3)
#pragma unroll
        for (int i = 0; i < 8; i++) {
#pragma unroll
            for (int t4 = 0; t4 < 4; t4++) {
                int jb = (rg + t4) & 3;
                gbuf[((w << 5) + (rg << 3) + i) * 32 + (bg << 2) + jb] =
                    pairsum(acc[i][jb]);
            }
        }
        __syncthreads();

        // cell update: warps 0..7, thread = (unit u_l, batch lane)
        if (w < 8) {
            int b = lane;
            float iv = xg0, fv = xg1, gv = xg2, ov = xg3;
#pragma unroll
            for (int q16 = 0; q16 < 16; q16++) {
                int base = (q16 << 10) + u_l * 32 + b;
                iv += gbuf[base + 0 * 256];
                fv += gbuf[base + 1 * 256];
                gv += gbuf[base + 2 * 256];
                ov += gbuf[base + 3 * 256];
            }
            iv = sigf(iv);
            fv = sigf(fv);
            gv = tanhfast(gv);
            ov = sigf(ov);
            float c_old = c_s[tid];
            float h_old = hp[hidx];
            float c_new = fv * c_old + iv * gv;
            float h_new = ov * tanhfast(c_new);
            float c_bl = 0.9f * c_new + 0.1f * c_old;
            float h_bl = 0.9f * h_new + 0.1f * h_old;
            c_s[tid] = c_bl;
            g_hbuf[dir][(s + 1) & 1][hidx] = h_bl;
            atomicAdd(&out[(size_t)t * (NB * HD) + b * HD + gu], h_bl);
        }

        dir_barrier(dir, gen);
        gen++;
    }
}

// ---------------------------------------------------------------------------
extern "C" void kernel_launch(void* const* d_in, const int* in_sizes, int n_in,
                              void* d_out, int out_size) {
    const float* x   = (const float*)d_in[0];
    const float* Wih = (const float*)d_in[1];
    const float* Whh = (const float*)d_in[2];
    const float* bih = (const float*)d_in[3];
    const float* bhh = (const float*)d_in[4];
    float* out = (float*)d_out;

    const int rec_smem = (16384 + 16384 + 16384 + 256) * (int)sizeof(float); // 197632 B
    cudaFuncSetAttribute(lstm_rec, cudaFuncAttributeMaxDynamicSharedMemorySize, rec_smem);

    xw_gemm<<<TSEQ * 32, 256>>>(x, Wih, bih, bhh, (float4*)out);
    lstm_rec<<<2 * NBLK_DIR, REC_THREADS, rec_smem>>>(Whh, out);
}

// round 7
// speedup vs baseline: 1.2844x; 1.2844x over previous
#include <cuda_runtime.h>

// Problem constants
#define TSEQ 1024
#define NB   32      // batch
#define ID   512     // input dim
#define HD   512     // hidden dim
#define GD   2048    // 4*H gate rows
#define NBLK_DIR 64  // persistent blocks per direction (8 hidden units each)
#define REC_THREADS 256

typedef unsigned long long ull;

// Scratch (device globals: no runtime allocation allowed)
__device__ float g_xw[(size_t)TSEQ * GD * NB];   // [t][g][b], 256MB
__device__ float g_hbuf[2][2][HD * NB];          // [dir][ping][u*32 + b] (plain layout)
__device__ unsigned g_barcnt[2];   // monotonic arrival counters (never reset)
__device__ unsigned g_bargen[2];   // monotonic generation

// ---------------------------------------------------------------------------
// packed fp32x2 ops (Blackwell)
// ---------------------------------------------------------------------------
__device__ __forceinline__ void ffma2(ull& d, ull a, ull b) {
    asm("fma.rn.f32x2 %0, %1, %2, %0;" : "+l"(d) : "l"(a), "l"(b));
}
__device__ __forceinline__ ull addf2(ull a, ull b) {
    ull r;
    asm("add.rn.f32x2 %0, %1, %2;" : "=l"(r) : "l"(a), "l"(b));
    return r;
}
__device__ __forceinline__ ull dup2(float x) {
    ull r;
    asm("mov.b64 %0, {%1, %1};" : "=l"(r) : "f"(x));
    return r;
}
__device__ __forceinline__ float pairsum(ull v) {
    float2 f = *reinterpret_cast<float2*>(&v);
    return f.x + f.y;
}

__device__ __forceinline__ unsigned atom_add_acqrel(unsigned* p, unsigned v) {
    unsigned old;
    asm volatile("atom.acq_rel.gpu.add.u32 %0, [%1], %2;"
                 : "=r"(old) : "l"(p), "r"(v) : "memory");
    return old;
}
__device__ __forceinline__ unsigned ld_acquire(const unsigned* p) {
    unsigned v;
    asm volatile("ld.acquire.gpu.u32 %0, [%1];" : "=r"(v) : "l"(p) : "memory");
    return v;
}
__device__ __forceinline__ void st_release(unsigned* p, unsigned v) {
    asm volatile("st.release.gpu.u32 [%0], %1;" :: "l"(p), "r"(v) : "memory");
}

__device__ __forceinline__ float sigf(float x) {
    return __fdividef(1.f, 1.f + __expf(-x));
}
__device__ __forceinline__ float tanhfast(float x) {
    return __fdividef(2.f, 1.f + __expf(-2.f * x)) - 1.f;
}

// ---------------------------------------------------------------------------
// xw[t][g][b] = sum_i x[t][b][i] * W_ih[g][i] + (b_ih[g] + b_hh[g])
// Also zeroes its 2KB slice of d_out.
// ---------------------------------------------------------------------------
__global__ __launch_bounds__(256) void xw_gemm(
    const float* __restrict__ x,
    const float* __restrict__ Wih,
    const float* __restrict__ bih,
    const float* __restrict__ bhh,
    float4* __restrict__ out4)
{
    __shared__ float xs[NB * 36];
    __shared__ float ws[64 * 32];

    if (threadIdx.x < 128)
        out4[(size_t)blockIdx.x * 128 + threadIdx.x] = make_float4(0.f, 0.f, 0.f, 0.f);

    int t   = blockIdx.x >> 5;
    int g0  = (blockIdx.x & 31) << 6;
    int tid = threadIdx.x;
    int gg  = tid >> 5;
    int b   = tid & 31;

    ull acc[8];
#pragma unroll
    for (int j = 0; j < 8; j++) acc[j] = 0ull;

    const float* xt = x + (size_t)t * NB * ID;

    for (int k0 = 0; k0 < ID; k0 += 32) {
#pragma unroll
        for (int r = 0; r < 4; r++) {
            int bl = (tid >> 5) + (r << 3);
            int kk = tid & 31;
            xs[bl * 36 + kk] = xt[bl * ID + k0 + kk];
        }
#pragma unroll
        for (int r = 0; r < 8; r++) {
            int gl = (tid >> 5) + (r << 3);
            int kk = tid & 31;
            ws[gl * 32 + kk] = Wih[(size_t)(g0 + gl) * ID + k0 + kk];
        }
        __syncthreads();

#pragma unroll
        for (int kk = 0; kk < 32; kk += 4) {
            ulonglong2 xv = *(const ulonglong2*)&xs[b * 36 + kk];
#pragma unroll
            for (int j = 0; j < 8; j++) {
                ulonglong2 wv = *(const ulonglong2*)&ws[(gg * 8 + j) * 32 + kk];
                ffma2(acc[j], xv.x, wv.x);
                ffma2(acc[j], xv.y, wv.y);
            }
        }
        __syncthreads();
    }

    float* outp = g_xw + (size_t)t * GD * NB;
#pragma unroll
    for (int j = 0; j < 8; j++) {
        int g = g0 + gg * 8 + j;
        outp[g * NB + b] = pairsum(acc[j]) + bih[g] + bhh[g];
    }
}

// ---------------------------------------------------------------------------
// Global spin barrier, per direction, monotonic (graph-replay safe)
// ---------------------------------------------------------------------------
__device__ __forceinline__ void dir_barrier(int dir, unsigned gen) {
    __syncthreads();
    if (threadIdx.x == 0) {
        unsigned old = atom_add_acqrel(&g_barcnt[dir], 1u);
        if (old == gen * (unsigned)NBLK_DIR + (NBLK_DIR - 1)) {
            st_release(&g_bargen[dir], gen + 1u);
        } else {
            while ((int)(ld_acquire(&g_bargen[dir]) - (gen + 1u)) < 0) { }
        }
    }
    __syncthreads();
}

// ---------------------------------------------------------------------------
// Persistent bidirectional zoneout-LSTM recurrence, 256 threads.
// 128 blocks: 0..63 fwd, 64..127 bwd. Block: 8 hidden units (32 gate rows) x 32 b.
// GEMV (scheme-b, batch-paired ffma2): lane = (ks0 = lane>>4, rg = (lane>>2)&3,
// bg = lane&3): tile = rows 8rg..8rg+7 x batches 8bg..8bg+7 x 32 k
// (k in [64w + 32ks0, +32)). Per k: 2 LDS.128 W scalars + 2 LDS.128 h +
// 8 dup-MOV + 32 FFMA2 -> 2 smem-bytes per FFMA2. acc = 32 ull (64 regs).
// ks0 halves folded via shfl_xor(16); 8 partial sets in gbuf (stride-34 rows).
// ---------------------------------------------------------------------------
__global__ __launch_bounds__(REC_THREADS, 1) void lstm_rec(
    const float* __restrict__ Whh, float* __restrict__ out)
{
    extern __shared__ float smem[];
    float* Wt   = smem;             // 64KB: Wt[k*32 + row]   (row = local gate-row 0..31)
    float* Hs   = smem + 16384;     // 64KB: Hs[u*32 + b]     (u = global hidden unit)
    float* gbuf = smem + 32768;     // 34KB: gbuf[w*1088 + row*34 + b]

    int bid  = blockIdx.x;
    int dir  = bid >> 6;
    int j0   = (bid & 63) << 3;
    int tid  = threadIdx.x;
    int w    = tid >> 5;
    int lane = tid & 31;
    int ks0  = lane >> 4;
    int rg   = (lane >> 2) & 3;
    int bg   = lane & 3;
    int u_l  = w;               // cell phase: unit-local 0..7
    int gu   = j0 + u_l;

    // Stage W_hh once: Wt[k*32 + row], row -> global W row (row>>3)*512 + j0 + (row&7)
#pragma unroll 4
    for (int i = 0; i < 64; i++) {
        int idx = tid + (i << 8);
        int row = idx >> 9;
        int k   = idx & 511;
        int gr  = ((row >> 3) << 9) + j0 + (row & 7);
        Wt[k * 32 + row] = Whh[(size_t)gr * HD + k];
    }

    // init h(step 0) = 0 (own units), c in registers
    float c_reg = 0.f;
    g_hbuf[dir][0][gu * 32 + lane] = 0.f;

    unsigned gen = ld_acquire(&g_bargen[dir]);
    dir_barrier(dir, gen);
    gen++;

    const float4* W4 = (const float4*)Wt;
    const float4* H4 = (const float4*)Hs;
    const int kbeg = (w << 6) + (ks0 << 5);

    for (int s = 0; s < TSEQ; s++) {
        int t = dir ? (TSEQ - 1 - s) : s;
        const float* xw_t = g_xw + (size_t)t * GD * NB;

        // prefetch xw for the cell phase (hidden under GEMV)
        float xg0 = xw_t[(0 * HD + gu) * NB + lane];
        float xg1 = xw_t[(1 * HD + gu) * NB + lane];
        float xg2 = xw_t[(2 * HD + gu) * NB + lane];
        float xg3 = xw_t[(3 * HD + gu) * NB + lane];

        // per-warp copy of its own h k-range [64w, 64w+64): float4 [512w, 512w+512)
        {
            const float4* hsrc = (const float4*)g_hbuf[dir][s & 1];
            float4* hdst = (float4*)Hs;
#pragma unroll
            for (int i = 0; i < 16; i++) {
                int idx = (w << 9) + (i << 5) + lane;
                hdst[idx] = __ldcg(&hsrc[idx]);
            }
            __syncwarp();   // order cross-lane STS -> LDS within this warp
        }

        // GEMV: 8 rows x 4 batch-pairs per lane over 32 k
        ull acc[8][4];
#pragma unroll
        for (int i = 0; i < 8; i++)
#pragma unroll
            for (int j = 0; j < 4; j++) acc[i][j] = 0ull;

#pragma unroll 4
        for (int kk = 0; kk < 32; kk++) {
            int k = kbeg + kk;
            float4 wA = W4[(k << 3) + (rg << 1)];       // rows 8rg..8rg+3
            float4 wB = W4[(k << 3) + (rg << 1) + 1];   // rows 8rg+4..8rg+7
            ulonglong2 hA = *(const ulonglong2*)&H4[(k << 3) + (bg << 1)];     // b 8bg..+3
            ulonglong2 hB = *(const ulonglong2*)&H4[(k << 3) + (bg << 1) + 1]; // b 8bg+4..+7
            float wf[8] = {wA.x, wA.y, wA.z, wA.w, wB.x, wB.y, wB.z, wB.w};
#pragma unroll
            for (int i = 0; i < 8; i++) {
                ull wd = dup2(wf[i]);
                ffma2(acc[i][0], wd, hA.x);
                ffma2(acc[i][1], wd, hA.y);
                ffma2(acc[i][2], wd, hB.x);
                ffma2(acc[i][3], wd, hB.y);
            }
        }

        // fold the two k-halves (lanes xor 16) -> full 64-k sums in both lanes
#pragma unroll
        for (int i = 0; i < 8; i++)
#pragma unroll
            for (int j = 0; j < 4; j++)
                acc[i][j] = addf2(acc[i][j], __shfl_xor_sync(0xFFFFFFFFu, acc[i][j], 16));

        // store partials: lane ks0 writes rows 8rg + 4ks0 + (0..3)
        {
            int i0 = ks0 << 2;
#pragma unroll
            for (int ii = 0; ii < 4; ii++) {
                int row = (rg << 3) + i0 + ii;
                float* gp = gbuf + w * 1088 + row * 34 + (bg << 3);
#pragma unroll
                for (int j = 0; j < 4; j++)
                    *(ull*)(gp + (j << 1)) = acc[i0 + ii][j];
            }
        }
        __syncthreads();

        // cell update: thread = (unit u_l = w, batch lane); 8 partial sets per gate
        {
            int b = lane;
            float iv = xg0, fv = xg1, gv = xg2, ov = xg3;
#pragma unroll
            for (int sw = 0; sw < 8; sw++) {
                const float* gp = gbuf + sw * 1088 + b;
                iv += gp[(0 * 8 + u_l) * 34];
                fv += gp[(1 * 8 + u_l) * 34];
                gv += gp[(2 * 8 + u_l) * 34];
                ov += gp[(3 * 8 + u_l) * 34];
            }
            iv = sigf(iv);
            fv = sigf(fv);
            gv = tanhfast(gv);
            ov = sigf(ov);
            float h_old = Hs[gu * 32 + b];
            float c_new = fv * c_reg + iv * gv;
            float h_new = ov * tanhfast(c_new);
            c_reg = 0.9f * c_new + 0.1f * c_reg;
            float h_bl = 0.9f * h_new + 0.1f * h_old;
            g_hbuf[dir][(s + 1) & 1][gu * 32 + b] = h_bl;
            // exactly two commutative fp32 adds per output element -> deterministic
            atomicAdd(&out[(size_t)t * (NB * HD) + b * HD + gu], h_bl);
        }

        dir_barrier(dir, gen);
        gen++;
    }
}

// ---------------------------------------------------------------------------
extern "C" void kernel_launch(void* const* d_in, const int* in_sizes, int n_in,
                              void* d_out, int out_size) {
    const float* x   = (const float*)d_in[0];
    const float* Wih = (const float*)d_in[1];
    const float* Whh = (const float*)d_in[2];
    const float* bih = (const float*)d_in[3];
    const float* bhh = (const float*)d_in[4];
    float* out = (float*)d_out;

    const int rec_smem = (16384 + 16384 + 8 * 1088) * (int)sizeof(float); // 165888 B
    cudaFuncSetAttribute(lstm_rec, cudaFuncAttributeMaxDynamicSharedMemorySize, rec_smem);

    xw_gemm<<<TSEQ * 32, 256>>>(x, Wih, bih, bhh, (float4*)out);
    lstm_rec<<<2 * NBLK_DIR, REC_THREADS, rec_smem>>>(Whh, out);
}

// round 8
// speedup vs baseline: 1.5618x; 1.2160x over previous
#include <cuda_runtime.h>

// Problem constants
#define TSEQ 1024
#define NB   32      // batch
#define ID   512     // input dim
#define HD   512     // hidden dim
#define GD   2048    // 4*H gate rows
#define NBLK_DIR 64  // persistent blocks per direction (8 hidden units each)
#define REC_THREADS 256

typedef unsigned long long ull;

// Scratch (device globals: no runtime allocation allowed)
__device__ float g_xw[(size_t)TSEQ * GD * NB];   // [t][g][b], 256MB
__device__ float g_hbuf[2][2][HD * NB];          // [dir][ping][u*32 + b]
__device__ unsigned g_barcnt[2];   // monotonic arrival counters (never reset)
__device__ unsigned g_bargen[2];   // monotonic generation

// ---------------------------------------------------------------------------
// packed fp32x2 ops (Blackwell)
// ---------------------------------------------------------------------------
__device__ __forceinline__ void ffma2(ull& d, ull a, ull b) {
    asm("fma.rn.f32x2 %0, %1, %2, %0;" : "+l"(d) : "l"(a), "l"(b));
}
__device__ __forceinline__ ull addf2(ull a, ull b) {
    ull r;
    asm("add.rn.f32x2 %0, %1, %2;" : "=l"(r) : "l"(a), "l"(b));
    return r;
}
__device__ __forceinline__ ull dup2(float x) {
    ull r;
    asm("mov.b64 %0, {%1, %1};" : "=l"(r) : "f"(x));
    return r;
}
__device__ __forceinline__ float pairsum(ull v) {
    float2 f = *reinterpret_cast<float2*>(&v);
    return f.x + f.y;
}

__device__ __forceinline__ unsigned atom_add_acqrel(unsigned* p, unsigned v) {
    unsigned old;
    asm volatile("atom.acq_rel.gpu.add.u32 %0, [%1], %2;"
                 : "=r"(old) : "l"(p), "r"(v) : "memory");
    return old;
}
__device__ __forceinline__ unsigned ld_acquire(const unsigned* p) {
    unsigned v;
    asm volatile("ld.acquire.gpu.u32 %0, [%1];" : "=r"(v) : "l"(p) : "memory");
    return v;
}
__device__ __forceinline__ void st_release(unsigned* p, unsigned v) {
    asm volatile("st.release.gpu.u32 [%0], %1;" :: "l"(p), "r"(v) : "memory");
}

__device__ __forceinline__ float sigf(float x) {
    return __fdividef(1.f, 1.f + __expf(-x));
}
__device__ __forceinline__ float tanhfast(float x) {
    return __fdividef(2.f, 1.f + __expf(-2.f * x)) - 1.f;
}

// ---------------------------------------------------------------------------
// xw[t][g][b] = sum_i x[t][b][i] * W_ih[g][i] + (b_ih[g] + b_hh[g])
// Also zeroes its 2KB slice of d_out.
// ---------------------------------------------------------------------------
__global__ __launch_bounds__(256) void xw_gemm(
    const float* __restrict__ x,
    const float* __restrict__ Wih,
    const float* __restrict__ bih,
    const float* __restrict__ bhh,
    float4* __restrict__ out4)
{
    __shared__ float xs[NB * 36];
    __shared__ float ws[64 * 32];

    if (threadIdx.x < 128)
        out4[(size_t)blockIdx.x * 128 + threadIdx.x] = make_float4(0.f, 0.f, 0.f, 0.f);

    int t   = blockIdx.x >> 5;
    int g0  = (blockIdx.x & 31) << 6;
    int tid = threadIdx.x;
    int gg  = tid >> 5;
    int b   = tid & 31;

    ull acc[8];
#pragma unroll
    for (int j = 0; j < 8; j++) acc[j] = 0ull;

    const float* xt = x + (size_t)t * NB * ID;

    for (int k0 = 0; k0 < ID; k0 += 32) {
#pragma unroll
        for (int r = 0; r < 4; r++) {
            int bl = (tid >> 5) + (r << 3);
            int kk = tid & 31;
            xs[bl * 36 + kk] = xt[bl * ID + k0 + kk];
        }
#pragma unroll
        for (int r = 0; r < 8; r++) {
            int gl = (tid >> 5) + (r << 3);
            int kk = tid & 31;
            ws[gl * 32 + kk] = Wih[(size_t)(g0 + gl) * ID + k0 + kk];
        }
        __syncthreads();

#pragma unroll
        for (int kk = 0; kk < 32; kk += 4) {
            ulonglong2 xv = *(const ulonglong2*)&xs[b * 36 + kk];
#pragma unroll
            for (int j = 0; j < 8; j++) {
                ulonglong2 wv = *(const ulonglong2*)&ws[(gg * 8 + j) * 32 + kk];
                ffma2(acc[j], xv.x, wv.x);
                ffma2(acc[j], xv.y, wv.y);
            }
        }
        __syncthreads();
    }

    float* outp = g_xw + (size_t)t * GD * NB;
#pragma unroll
    for (int j = 0; j < 8; j++) {
        int g = g0 + gg * 8 + j;
        outp[g * NB + b] = pairsum(acc[j]) + bih[g] + bhh[g];
    }
}

// ---------------------------------------------------------------------------
// Global spin barrier, per direction, monotonic (graph-replay safe)
// ---------------------------------------------------------------------------
__device__ __forceinline__ void dir_barrier(int dir, unsigned gen) {
    __syncthreads();
    if (threadIdx.x == 0) {
        unsigned old = atom_add_acqrel(&g_barcnt[dir], 1u);
        if (old == gen * (unsigned)NBLK_DIR + (NBLK_DIR - 1)) {
            st_release(&g_bargen[dir], gen + 1u);
        } else {
            while ((int)(ld_acquire(&g_bargen[dir]) - (gen + 1u)) < 0) { }
        }
    }
    __syncthreads();
}

// ---------------------------------------------------------------------------
// Persistent bidirectional zoneout-LSTM recurrence, 256 threads.
// 128 blocks: 0..63 fwd, 64..127 bwd. Block: 8 hidden units (32 gate rows) x 32 b.
// GEMV (batch-paired ffma2): lane = (ks0 = lane>>4, rg = (lane>>2)&3, bg = lane&3):
// tile = rows 8rg..8rg+7 x batches 8bg..8bg+7 x 32 k (k in [64w+32ks0, +32)).
// Per k: 2 LDS.128 W + 2 LDS.128 h + 8 dup-MOV + 32 FFMA2 -> 2 smem-B/FFMA2.
// Epilogue: STATIC-index value-selects + one shfl_xor(16) exchange per value
// (no dynamic register-array indexing -> no local-memory demotion).
// ---------------------------------------------------------------------------
__global__ __launch_bounds__(REC_THREADS, 1) void lstm_rec(
    const float* __restrict__ Whh, float* __restrict__ out)
{
    extern __shared__ float smem[];
    float* Wt   = smem;             // 64KB: Wt[k*32 + row]
    float* Hs   = smem + 16384;     // 64KB: Hs[u*32 + b]
    float* gbuf = smem + 32768;     // 34KB: gbuf[w*1088 + row*34 + b]

    int bid  = blockIdx.x;
    int dir  = bid >> 6;
    int j0   = (bid & 63) << 3;
    int tid  = threadIdx.x;
    int w    = tid >> 5;
    int lane = tid & 31;
    int ks0  = lane >> 4;
    int rg   = (lane >> 2) & 3;
    int bg   = lane & 3;
    int u_l  = w;               // cell phase: unit-local 0..7
    int gu   = j0 + u_l;

    // Stage W_hh once: Wt[k*32 + row], row -> global W row (row>>3)*512 + j0 + (row&7)
#pragma unroll 4
    for (int i = 0; i < 64; i++) {
        int idx = tid + (i << 8);
        int row = idx >> 9;
        int k   = idx & 511;
        int gr  = ((row >> 3) << 9) + j0 + (row & 7);
        Wt[k * 32 + row] = Whh[(size_t)gr * HD + k];
    }

    // init h(step 0) = 0 (own units), c in registers
    float c_reg = 0.f;
    g_hbuf[dir][0][gu * 32 + lane] = 0.f;

    unsigned gen = ld_acquire(&g_bargen[dir]);
    dir_barrier(dir, gen);
    gen++;

    const float4* W4 = (const float4*)Wt;
    const float4* H4 = (const float4*)Hs;
    const int kbeg = (w << 6) + (ks0 << 5);

    for (int s = 0; s < TSEQ; s++) {
        int t = dir ? (TSEQ - 1 - s) : s;
        const float* xw_t = g_xw + (size_t)t * GD * NB;

        // prefetch xw for the cell phase (hidden under GEMV)
        float xg0 = xw_t[(0 * HD + gu) * NB + lane];
        float xg1 = xw_t[(1 * HD + gu) * NB + lane];
        float xg2 = xw_t[(2 * HD + gu) * NB + lane];
        float xg3 = xw_t[(3 * HD + gu) * NB + lane];

        // per-warp copy of its own h k-range [64w, 64w+64): float4 [512w, 512w+512)
        {
            const float4* hsrc = (const float4*)g_hbuf[dir][s & 1];
            float4* hdst = (float4*)Hs;
#pragma unroll
            for (int i = 0; i < 16; i++) {
                int idx = (w << 9) + (i << 5) + lane;
                hdst[idx] = __ldcg(&hsrc[idx]);
            }
            __syncwarp();   // order cross-lane STS -> LDS within this warp
        }

        // GEMV: 8 rows x 4 batch-pairs per lane over 32 k
        ull acc[8][4];
#pragma unroll
        for (int i = 0; i < 8; i++)
#pragma unroll
            for (int j = 0; j < 4; j++) acc[i][j] = 0ull;

#pragma unroll 4
        for (int kk = 0; kk < 32; kk++) {
            int k = kbeg + kk;
            float4 wA = W4[(k << 3) + (rg << 1)];       // rows 8rg..8rg+3
            float4 wB = W4[(k << 3) + (rg << 1) + 1];   // rows 8rg+4..8rg+7
            ulonglong2 hA = *(const ulonglong2*)&H4[(k << 3) + (bg << 1)];     // b 8bg..+3
            ulonglong2 hB = *(const ulonglong2*)&H4[(k << 3) + (bg << 1) + 1]; // b 8bg+4..+7
            float wf[8] = {wA.x, wA.y, wA.z, wA.w, wB.x, wB.y, wB.z, wB.w};
#pragma unroll
            for (int i = 0; i < 8; i++) {
                ull wd = dup2(wf[i]);
                ffma2(acc[i][0], wd, hA.x);
                ffma2(acc[i][1], wd, hA.y);
                ffma2(acc[i][2], wd, hB.x);
                ffma2(acc[i][3], wd, hB.y);
            }
        }

        // fold k-halves + store: STATIC indices only (value-select, never acc[runtime]).
        // ks0=0 lane keeps batch-pairs j=0,1 (b 8bg..8bg+3); ks0=1 keeps j=2,3 (+4..+7).
        // Each lane sends the half its partner (lane^16) needs, adds what it receives.
        {
            float* gp0 = gbuf + w * 1088 + (bg << 3) + (ks0 << 2);
#pragma unroll
            for (int i = 0; i < 8; i++) {
                ull s0 = ks0 ? acc[i][0] : acc[i][2];
                ull s1 = ks0 ? acc[i][1] : acc[i][3];
                ull r0 = __shfl_xor_sync(0xFFFFFFFFu, s0, 16);
                ull r1 = __shfl_xor_sync(0xFFFFFFFFu, s1, 16);
                ull k0 = ks0 ? acc[i][2] : acc[i][0];
                ull k1 = ks0 ? acc[i][3] : acc[i][1];
                ull v0 = addf2(k0, r0);
                ull v1 = addf2(k1, r1);
                float* gp = gp0 + ((rg << 3) + i) * 34;
                *(ull*)gp = v0;
                *(ull*)(gp + 2) = v1;
            }
        }
        __syncthreads();

        // cell update: thread = (unit u_l = w, batch lane); 8 partial sets per gate
        {
            int b = lane;
            float iv = xg0, fv = xg1, gv = xg2, ov = xg3;
#pragma unroll
            for (int sw = 0; sw < 8; sw++) {
                const float* gp = gbuf + sw * 1088 + b;
                iv += gp[(0 * 8 + u_l) * 34];
                fv += gp[(1 * 8 + u_l) * 34];
                gv += gp[(2 * 8 + u_l) * 34];
                ov += gp[(3 * 8 + u_l) * 34];
            }
            iv = sigf(iv);
            fv = sigf(fv);
            gv = tanhfast(gv);
            ov = sigf(ov);
            float h_old = Hs[gu * 32 + b];
            float c_new = fv * c_reg + iv * gv;
            float h_new = ov * tanhfast(c_new);
            c_reg = 0.9f * c_new + 0.1f * c_reg;
            float h_bl = 0.9f * h_new + 0.1f * h_old;
            g_hbuf[dir][(s + 1) & 1][gu * 32 + b] = h_bl;
            // exactly two commutative fp32 adds per output element -> deterministic
            atomicAdd(&out[(size_t)t * (NB * HD) + b * HD + gu], h_bl);
        }

        dir_barrier(dir, gen);
        gen++;
    }
}

// ---------------------------------------------------------------------------
extern "C" void kernel_launch(void* const* d_in, const int* in_sizes, int n_in,
                              void* d_out, int out_size) {
    const float* x   = (const float*)d_in[0];
    const float* Wih = (const float*)d_in[1];
    const float* Whh = (const float*)d_in[2];
    const float* bih = (const float*)d_in[3];
    const float* bhh = (const float*)d_in[4];
    float* out = (float*)d_out;

    const int rec_smem = (16384 + 16384 + 8 * 1088) * (int)sizeof(float); // 165888 B
    cudaFuncSetAttribute(lstm_rec, cudaFuncAttributeMaxDynamicSharedMemorySize, rec_smem);

    xw_gemm<<<TSEQ * 32, 256>>>(x, Wih, bih, bhh, (float4*)out);
    lstm_rec<<<2 * NBLK_DIR, REC_THREADS, rec_smem>>>(Whh, out);
}